// round 13
// baseline (speedup 1.0000x reference)
#include <cuda_runtime.h>
#include <cuda_bf16.h>
#include <cuda_fp16.h>
#include <mma.h>

using namespace nvcuda;

// 2-layer GCN. Ahat = D^-1/2 (A+I) D^-1/2, factored:
//   agg(h)[d] = dis[d] * sum_{s in N(d)} dis[s] * h[s]
// int32 edges. One persistent prep kernel (degree/scan/scatter with grid
// barriers), WMMA fp16 GEMMs (fp32 accumulate), fp16 intermediates,
// warp-per-node segment aggregation.

#define NN 50000
#define NE 800000
#define ET (NN + NE)
#define NBLK ((NN + 255) / 256)   // 196 node ranges
#define PNB 592                   // persistent prep blocks (4/SM)

// ---- device scratch (static, no allocation) ----
__device__ __half g_h1[NN * 128];    // fp16 x@W1
__device__ __half g_a1[NN * 128];    // fp16 relu(agg)
__device__ __half g_h2[NN * 64];     // fp16 a1@W2
__device__ int    g_deg[NN];         // zeroed by tail of previous launch
__device__ float  g_dis[NN];
__device__ int    g_off[NN + 1];
__device__ int    g_cnt[NN];         // zeroed by tail of previous launch
__device__ int    g_src[ET];
__device__ int    g_bsum[NBLK];
__device__ int    g_boff[NBLK];
__device__ volatile unsigned g_bar_gen;
__device__ unsigned g_bar_cnt;

__device__ __forceinline__ float4 h4_to_f4(uint2 u) {
    __half2 a = *reinterpret_cast<__half2*>(&u.x);
    __half2 b = *reinterpret_cast<__half2*>(&u.y);
    float2 fa = __half22float2(a), fb = __half22float2(b);
    return make_float4(fa.x, fa.y, fb.x, fb.y);
}
__device__ __forceinline__ float2 h2_to_f2(unsigned u) {
    __half2 a = *reinterpret_cast<__half2*>(&u);
    return __half22float2(a);
}
__device__ __forceinline__ uint2 f4_to_h4(float4 v) {
    __half2 h0 = __floats2half2_rn(v.x, v.y);
    __half2 h1 = __floats2half2_rn(v.z, v.w);
    uint2 r;
    r.x = *reinterpret_cast<unsigned*>(&h0);
    r.y = *reinterpret_cast<unsigned*>(&h1);
    return r;
}

// grid-wide barrier for the persistent prep kernel (all PNB blocks resident)
__device__ __forceinline__ void grid_bar() {
    __syncthreads();
    if (threadIdx.x == 0) {
        unsigned gen = g_bar_gen;
        __threadfence();
        if (atomicAdd(&g_bar_cnt, 1u) == PNB - 1) {
            atomicExch(&g_bar_cnt, 0u);
            __threadfence();
            g_bar_gen = gen + 1;
        } else {
            while (g_bar_gen == gen) __nanosleep(32);
        }
    }
    __syncthreads();
    __threadfence();
}

// ---------------------------------------------------------------------------
// Persistent prep: degree -> scan(block sums, top scan, offsets+dis) -> scatter
__global__ void __launch_bounds__(256) prep_kernel(const int* __restrict__ ei) {
    __shared__ int wsum[8];
    const int tid = threadIdx.x, bid = blockIdx.x;
    const int lane = tid & 31, w = tid >> 5;
    const int gtid = bid * 256 + tid;

    // ---- Phase A: degree histogram (int4 = 4 dst per thread) ----
    const int4* d4 = (const int4*)(ei + NE);
    #pragma unroll 2
    for (int i = gtid; i < NE / 4; i += PNB * 256) {
        int4 d = d4[i];
        atomicAdd(&g_deg[d.x], 1);
        atomicAdd(&g_deg[d.y], 1);
        atomicAdd(&g_deg[d.z], 1);
        atomicAdd(&g_deg[d.w], 1);
    }
    grid_bar();

    // ---- Phase B1: per-range block sums (ranges 0..NBLK-1) ----
    int v = 0;
    if (bid < NBLK) {
        int i = bid * 256 + tid;
        v = (i < NN) ? g_deg[i] + 1 : 0;       // +1 self loop
        int x = v;
        #pragma unroll
        for (int d = 16; d > 0; d >>= 1) x += __shfl_down_sync(0xffffffffu, x, d);
        if (lane == 0) wsum[w] = x;
        __syncthreads();
        if (tid < 8) {
            int y = wsum[tid];
            #pragma unroll
            for (int d = 4; d > 0; d >>= 1) y += __shfl_down_sync(0xffu, y, d);
            if (tid == 0) g_bsum[bid] = y;
        }
    }
    grid_bar();

    // ---- Phase B2: block 0 scans the NBLK range sums ----
    if (bid == 0) {
        int bv = (tid < NBLK) ? g_bsum[tid] : 0;
        int bx = bv;
        #pragma unroll
        for (int d = 1; d < 32; d <<= 1) {
            int t = __shfl_up_sync(0xffffffffu, bx, d);
            if (lane >= d) bx += t;
        }
        if (lane == 31) wsum[w] = bx;
        __syncthreads();
        if (w == 0 && lane < 8) {
            int y = wsum[lane];
            #pragma unroll
            for (int d = 1; d < 8; d <<= 1) {
                int t = __shfl_up_sync(0xffu, y, d);
                if (lane >= d) y += t;
            }
            wsum[lane] = y;
        }
        __syncthreads();
        int excl = bx - bv + (w > 0 ? wsum[w - 1] : 0);
        if (tid < NBLK) g_boff[tid] = excl;
        if (tid == NBLK - 1) g_off[NN] = excl + bv;   // == ET
    }
    grid_bar();

    // ---- Phase B3: local exclusive scan + dis + offsets (reuses v) ----
    if (bid < NBLK) {
        __syncthreads();                 // wsum reuse
        int i = bid * 256 + tid;
        if (i < NN) g_dis[i] = rsqrtf((float)v);
        int x = v;
        #pragma unroll
        for (int d = 1; d < 32; d <<= 1) {
            int t = __shfl_up_sync(0xffffffffu, x, d);
            if (lane >= d) x += t;
        }
        if (lane == 31) wsum[w] = x;
        __syncthreads();
        if (w == 0 && lane < 8) {
            int y = wsum[lane];
            #pragma unroll
            for (int d = 1; d < 8; d <<= 1) {
                int t = __shfl_up_sync(0xffu, y, d);
                if (lane >= d) y += t;
            }
            wsum[lane] = y;
        }
        __syncthreads();
        int excl = x - v + (w > 0 ? wsum[w - 1] : 0) + g_boff[bid];
        if (i < NN) g_off[i] = excl;
    }
    grid_bar();

    // ---- Phase C: scatter edges (+self loops) into dst-sorted order ----
    #pragma unroll 4
    for (int e = gtid; e < ET; e += PNB * 256) {
        int s, d;
        if (e < NE) { s = ei[e]; d = ei[NE + e]; }
        else        { s = d = e - NE; }
        int pos = g_off[d] + atomicAdd(&g_cnt[d], 1);
        g_src[pos] = s;
    }
}

// ---------------------------------------------------------------------------
// Tensor-core GEMM 1: g_h1[M,128] = fp16( A[M,128] @ B[128,128] )
__global__ void __launch_bounds__(256) wgemm1(
    const float* __restrict__ A, const float* __restrict__ B, int M)
{
    constexpr int LDA = 40, LDB = 136;
    __shared__ __half As[128 * LDA];
    __shared__ __half Bs[32 * LDB];
    __shared__ float  cst[8][256];

    const int tid = threadIdx.x;
    const int wid = tid >> 5;
    const int lane = tid & 31;
    const int block_row = blockIdx.x * 128;
    const int warpM = wid & 3;
    const int warpN = wid >> 2;

    wmma::fragment<wmma::accumulator, 16, 16, 16, float> cf[2][4];
    #pragma unroll
    for (int i = 0; i < 2; i++)
        #pragma unroll
        for (int j = 0; j < 4; j++) wmma::fill_fragment(cf[i][j], 0.f);

    const int a_row = tid >> 1;
    const int a_cg  = (tid & 1) * 16;
    const int b_row = tid >> 3;
    const int b_cg  = (tid & 7) * 16;

    for (int t = 0; t < 4; t++) {
        int k0 = t * 32;
        {
            int grow = block_row + a_row;
            float4 v0 = make_float4(0.f,0.f,0.f,0.f), v1 = v0, v2 = v0, v3 = v0;
            if (grow < M) {
                const float4* p = (const float4*)&A[(size_t)grow * 128 + k0 + a_cg];
                v0 = p[0]; v1 = p[1]; v2 = p[2]; v3 = p[3];
            }
            uint2* dst = (uint2*)&As[a_row * LDA + a_cg];
            dst[0] = f4_to_h4(v0); dst[1] = f4_to_h4(v1);
            dst[2] = f4_to_h4(v2); dst[3] = f4_to_h4(v3);
        }
        {
            const float4* p = (const float4*)&B[(size_t)(k0 + b_row) * 128 + b_cg];
            float4 v0 = p[0], v1 = p[1], v2 = p[2], v3 = p[3];
            uint2* dst = (uint2*)&Bs[b_row * LDB + b_cg];
            dst[0] = f4_to_h4(v0); dst[1] = f4_to_h4(v1);
            dst[2] = f4_to_h4(v2); dst[3] = f4_to_h4(v3);
        }
        __syncthreads();

        #pragma unroll
        for (int ks = 0; ks < 2; ks++) {
            wmma::fragment<wmma::matrix_a, 16, 16, 16, __half, wmma::row_major> af[2];
            wmma::fragment<wmma::matrix_b, 16, 16, 16, __half, wmma::row_major> bf[4];
            #pragma unroll
            for (int i = 0; i < 2; i++)
                wmma::load_matrix_sync(af[i], &As[(warpM * 32 + i * 16) * LDA + ks * 16], LDA);
            #pragma unroll
            for (int j = 0; j < 4; j++)
                wmma::load_matrix_sync(bf[j], &Bs[(ks * 16) * LDB + warpN * 64 + j * 16], LDB);
            #pragma unroll
            for (int i = 0; i < 2; i++)
                #pragma unroll
                for (int j = 0; j < 4; j++)
                    wmma::mma_sync(cf[i][j], af[i], bf[j], cf[i][j]);
        }
        __syncthreads();
    }

    #pragma unroll
    for (int i = 0; i < 2; i++) {
        #pragma unroll
        for (int j = 0; j < 4; j++) {
            wmma::store_matrix_sync(cst[wid], cf[i][j], 16, wmma::mem_row_major);
            __syncwarp();
            int r  = lane >> 1;
            int co = (lane & 1) * 8;
            int grow = block_row + warpM * 32 + i * 16 + r;
            if (grow < M) {
                const float* s = &cst[wid][r * 16 + co];
                __half2 h[4];
                h[0] = __floats2half2_rn(s[0], s[1]);
                h[1] = __floats2half2_rn(s[2], s[3]);
                h[2] = __floats2half2_rn(s[4], s[5]);
                h[3] = __floats2half2_rn(s[6], s[7]);
                *(uint4*)&g_h1[(size_t)grow * 128 + warpN * 64 + j * 16 + co] = *(uint4*)h;
            }
            __syncwarp();
        }
    }
}

// Tensor-core GEMM 2: g_h2[M,64] = fp16( g_a1[M,128] @ B[128,64] ), A fp16.
__global__ void __launch_bounds__(256) wgemm2(
    const float* __restrict__ B, int M)
{
    constexpr int LDA = 40, LDB = 72;
    __shared__ __half As[128 * LDA];
    __shared__ __half Bs[32 * LDB];
    __shared__ float  cst[8][256];

    const int tid = threadIdx.x;
    const int wid = tid >> 5;
    const int lane = tid & 31;
    const int block_row = blockIdx.x * 128;
    const int warpM = wid & 3;
    const int warpN = wid >> 2;

    wmma::fragment<wmma::accumulator, 16, 16, 16, float> cf[2][2];
    #pragma unroll
    for (int i = 0; i < 2; i++)
        #pragma unroll
        for (int j = 0; j < 2; j++) wmma::fill_fragment(cf[i][j], 0.f);

    const int a_row = tid >> 1;
    const int a_cg  = (tid & 1) * 16;
    const int b_row = tid >> 2;
    const int b_cg  = (tid & 3) * 16;

    for (int t = 0; t < 4; t++) {
        int k0 = t * 32;
        {
            int grow = block_row + a_row;
            uint4 v0 = make_uint4(0u,0u,0u,0u), v1 = v0;
            if (grow < M) {
                const uint4* p = (const uint4*)&g_a1[(size_t)grow * 128 + k0 + a_cg];
                v0 = p[0]; v1 = p[1];
            }
            *(uint4*)&As[a_row * LDA + a_cg]     = v0;
            *(uint4*)&As[a_row * LDA + a_cg + 8] = v1;
        }
        if (b_row < 32) {
            const float4* p = (const float4*)&B[(size_t)(k0 + b_row) * 64 + b_cg];
            float4 v0 = p[0], v1 = p[1], v2 = p[2], v3 = p[3];
            uint2* dst = (uint2*)&Bs[b_row * LDB + b_cg];
            dst[0] = f4_to_h4(v0); dst[1] = f4_to_h4(v1);
            dst[2] = f4_to_h4(v2); dst[3] = f4_to_h4(v3);
        }
        __syncthreads();

        #pragma unroll
        for (int ks = 0; ks < 2; ks++) {
            wmma::fragment<wmma::matrix_a, 16, 16, 16, __half, wmma::row_major> af[2];
            wmma::fragment<wmma::matrix_b, 16, 16, 16, __half, wmma::row_major> bf[2];
            #pragma unroll
            for (int i = 0; i < 2; i++)
                wmma::load_matrix_sync(af[i], &As[(warpM * 32 + i * 16) * LDA + ks * 16], LDA);
            #pragma unroll
            for (int j = 0; j < 2; j++)
                wmma::load_matrix_sync(bf[j], &Bs[(ks * 16) * LDB + warpN * 32 + j * 16], LDB);
            #pragma unroll
            for (int i = 0; i < 2; i++)
                #pragma unroll
                for (int j = 0; j < 2; j++)
                    wmma::mma_sync(cf[i][j], af[i], bf[j], cf[i][j]);
        }
        __syncthreads();
    }

    #pragma unroll
    for (int i = 0; i < 2; i++) {
        #pragma unroll
        for (int j = 0; j < 2; j++) {
            wmma::store_matrix_sync(cst[wid], cf[i][j], 16, wmma::mem_row_major);
            __syncwarp();
            int r  = lane >> 1;
            int co = (lane & 1) * 8;
            int grow = block_row + warpM * 32 + i * 16 + r;
            if (grow < M) {
                const float* s = &cst[wid][r * 16 + co];
                __half2 h[4];
                h[0] = __floats2half2_rn(s[0], s[1]);
                h[1] = __floats2half2_rn(s[2], s[3]);
                h[2] = __floats2half2_rn(s[4], s[5]);
                h[3] = __floats2half2_rn(s[6], s[7]);
                *(uint4*)&g_h2[(size_t)grow * 64 + warpN * 32 + j * 16 + co] = *(uint4*)h;
            }
            __syncwarp();
        }
    }
}

// ---------------------------------------------------------------------------
// Segment aggregation: warp per node; fp16 gathers, fp32 accumulate,
// fp16 store of a1.
__global__ void __launch_bounds__(256) agg128_relu(
    const float* __restrict__ bias)
{
    int gw = (blockIdx.x * blockDim.x + threadIdx.x) >> 5;
    int lane = threadIdx.x & 31;
    if (gw >= NN) return;
    int beg = g_off[gw], end = g_off[gw + 1];
    int c4 = lane * 4;

    float4 acc = make_float4(0.f, 0.f, 0.f, 0.f);
    int idx = beg;
    for (; idx + 4 <= end; idx += 4) {
        int s0 = g_src[idx + 0];
        int s1 = g_src[idx + 1];
        int s2 = g_src[idx + 2];
        int s3 = g_src[idx + 3];
        float n0 = g_dis[s0], n1 = g_dis[s1], n2 = g_dis[s2], n3 = g_dis[s3];
        uint2 u0 = *(const uint2*)(g_h1 + (size_t)s0 * 128 + c4);
        uint2 u1 = *(const uint2*)(g_h1 + (size_t)s1 * 128 + c4);
        uint2 u2 = *(const uint2*)(g_h1 + (size_t)s2 * 128 + c4);
        uint2 u3 = *(const uint2*)(g_h1 + (size_t)s3 * 128 + c4);
        float4 v0 = h4_to_f4(u0);
        float4 v1 = h4_to_f4(u1);
        float4 v2 = h4_to_f4(u2);
        float4 v3 = h4_to_f4(u3);
        acc.x = fmaf(n0, v0.x, acc.x); acc.y = fmaf(n0, v0.y, acc.y);
        acc.z = fmaf(n0, v0.z, acc.z); acc.w = fmaf(n0, v0.w, acc.w);
        acc.x = fmaf(n1, v1.x, acc.x); acc.y = fmaf(n1, v1.y, acc.y);
        acc.z = fmaf(n1, v1.z, acc.z); acc.w = fmaf(n1, v1.w, acc.w);
        acc.x = fmaf(n2, v2.x, acc.x); acc.y = fmaf(n2, v2.y, acc.y);
        acc.z = fmaf(n2, v2.z, acc.z); acc.w = fmaf(n2, v2.w, acc.w);
        acc.x = fmaf(n3, v3.x, acc.x); acc.y = fmaf(n3, v3.y, acc.y);
        acc.z = fmaf(n3, v3.z, acc.z); acc.w = fmaf(n3, v3.w, acc.w);
    }
    for (; idx < end; idx++) {
        int s = g_src[idx];
        float n = g_dis[s];
        float4 v = h4_to_f4(*(const uint2*)(g_h1 + (size_t)s * 128 + c4));
        acc.x = fmaf(n, v.x, acc.x); acc.y = fmaf(n, v.y, acc.y);
        acc.z = fmaf(n, v.z, acc.z); acc.w = fmaf(n, v.w, acc.w);
    }
    float dd = g_dis[gw];
    float4 bb = *(const float4*)(bias + c4);
    acc.x = fmaxf(fmaf(dd, acc.x, bb.x), 0.f);
    acc.y = fmaxf(fmaf(dd, acc.y, bb.y), 0.f);
    acc.z = fmaxf(fmaf(dd, acc.z, bb.z), 0.f);
    acc.w = fmaxf(fmaf(dd, acc.w, bb.w), 0.f);
    *(uint2*)&g_a1[(size_t)gw * 128 + c4] = f4_to_h4(acc);
}

// last kernel: also zeroes g_deg/g_cnt for the next launch
__global__ void __launch_bounds__(256) agg64_out(
    const float* __restrict__ bias, float* __restrict__ OUT)
{
    int gw = (blockIdx.x * blockDim.x + threadIdx.x) >> 5;
    int lane = threadIdx.x & 31;
    if (gw >= NN) return;
    int beg = g_off[gw], end = g_off[gw + 1];
    int c2 = lane * 2;

    float2 acc = make_float2(0.f, 0.f);
    int idx = beg;
    for (; idx + 4 <= end; idx += 4) {
        int s0 = g_src[idx + 0];
        int s1 = g_src[idx + 1];
        int s2 = g_src[idx + 2];
        int s3 = g_src[idx + 3];
        float n0 = g_dis[s0], n1 = g_dis[s1], n2 = g_dis[s2], n3 = g_dis[s3];
        float2 v0 = h2_to_f2(*(const unsigned*)(g_h2 + (size_t)s0 * 64 + c2));
        float2 v1 = h2_to_f2(*(const unsigned*)(g_h2 + (size_t)s1 * 64 + c2));
        float2 v2 = h2_to_f2(*(const unsigned*)(g_h2 + (size_t)s2 * 64 + c2));
        float2 v3 = h2_to_f2(*(const unsigned*)(g_h2 + (size_t)s3 * 64 + c2));
        acc.x = fmaf(n0, v0.x, acc.x); acc.y = fmaf(n0, v0.y, acc.y);
        acc.x = fmaf(n1, v1.x, acc.x); acc.y = fmaf(n1, v1.y, acc.y);
        acc.x = fmaf(n2, v2.x, acc.x); acc.y = fmaf(n2, v2.y, acc.y);
        acc.x = fmaf(n3, v3.x, acc.x); acc.y = fmaf(n3, v3.y, acc.y);
    }
    for (; idx < end; idx++) {
        int s = g_src[idx];
        float n = g_dis[s];
        float2 v = h2_to_f2(*(const unsigned*)(g_h2 + (size_t)s * 64 + c2));
        acc.x = fmaf(n, v.x, acc.x); acc.y = fmaf(n, v.y, acc.y);
    }
    float dd = g_dis[gw];
    float2 bb = *(const float2*)(bias + c2);
    acc.x = fmaf(dd, acc.x, bb.x);
    acc.y = fmaf(dd, acc.y, bb.y);
    *(float2*)(OUT + (size_t)gw * 64 + c2) = acc;

    if (lane == 0) { g_deg[gw] = 0; g_cnt[gw] = 0; }
}

// ---------------------------------------------------------------------------
extern "C" void kernel_launch(void* const* d_in, const int* in_sizes, int n_in,
                              void* d_out, int out_size) {
    const float* x  = (const float*)d_in[0];
    const int*   ei = (const int*)d_in[1];
    const float* W1 = (const float*)d_in[2];
    const float* b1 = (const float*)d_in[3];
    const float* W2 = (const float*)d_in[4];
    const float* b2 = (const float*)d_in[5];
    float*       out = (float*)d_out;

    static cudaStream_t s2 = nullptr;
    static cudaEvent_t evFork = nullptr, evJoin = nullptr;
    if (s2 == nullptr) {
        cudaStreamCreateWithFlags(&s2, cudaStreamNonBlocking);
        cudaEventCreateWithFlags(&evFork, cudaEventDisableTiming);
        cudaEventCreateWithFlags(&evJoin, cudaEventDisableTiming);
    }

    const int TB = 256;

    // fork: wgemm1 (x@W1, independent of graph prep) on s2
    cudaEventRecord(evFork, 0);
    cudaStreamWaitEvent(s2, evFork, 0);
    wgemm1<<<(NN + 127) / 128, 256, 0, s2>>>(x, W1, NN);
    cudaEventRecord(evJoin, s2);

    // graph prep: single persistent kernel
    prep_kernel<<<PNB, 256>>>(ei);

    // join, then rest of the pipeline
    cudaStreamWaitEvent(0, evJoin, 0);
    agg128_relu<<<(NN * 32 + TB - 1) / TB, TB>>>(b1);
    wgemm2<<<(NN + 127) / 128, 256>>>(W2, NN);
    agg64_out<<<(NN * 32 + TB - 1) / TB, TB>>>(b2, out);
}

// round 14
// speedup vs baseline: 1.1322x; 1.1322x over previous
#include <cuda_runtime.h>
#include <cuda_bf16.h>
#include <cuda_fp16.h>
#include <mma.h>

using namespace nvcuda;

// 2-layer GCN. Ahat = D^-1/2 (A+I) D^-1/2, factored:
//   agg(h)[d] = dis[d] * sum_{s in N(d)} dis[s] * h[s]
// int32 edges; counting-sort by dst; warp-per-node segment aggregation with
// fp16 gathers; WMMA fp16 GEMMs (fp32 accumulate); a1 stored fp16.
// R12 launch structure (separate prep kernels, wgemm1 overlapped on stream 2).

#define NN 50000
#define NE 800000
#define ET (NN + NE)
#define NBLK ((NN + 255) / 256)

// ---- device scratch (static, no allocation) ----
__device__ __half g_h1[NN * 128];    // fp16 x@W1
__device__ __half g_a1[NN * 128];    // fp16 relu(agg)
__device__ __half g_h2[NN * 64];     // fp16 a1@W2
__device__ int    g_deg[NN];         // zeroed by tail of previous launch
__device__ float  g_dis[NN];
__device__ int    g_off[NN + 1];
__device__ int    g_cnt[NN];         // zeroed by tail of previous launch
__device__ int    g_src[ET];
__device__ int    g_bsum[NBLK];
__device__ int    g_boff[NBLK];
__device__ int    g_tick;            // reset by last scan block

__device__ __forceinline__ float4 h4_to_f4(uint2 u) {
    __half2 a = *reinterpret_cast<__half2*>(&u.x);
    __half2 b = *reinterpret_cast<__half2*>(&u.y);
    float2 fa = __half22float2(a), fb = __half22float2(b);
    return make_float4(fa.x, fa.y, fb.x, fb.y);
}
__device__ __forceinline__ float2 h2_to_f2(unsigned u) {
    __half2 a = *reinterpret_cast<__half2*>(&u);
    return __half22float2(a);
}
__device__ __forceinline__ uint2 f4_to_h4(float4 v) {
    __half2 h0 = __floats2half2_rn(v.x, v.y);
    __half2 h1 = __floats2half2_rn(v.z, v.w);
    uint2 r;
    r.x = *reinterpret_cast<unsigned*>(&h0);
    r.y = *reinterpret_cast<unsigned*>(&h1);
    return r;
}

// ---------------------------------------------------------------------------
__global__ void degree_kernel(const int* __restrict__ ei) {
    int e = blockIdx.x * blockDim.x + threadIdx.x;
    if (e < NE / 2) {
        int2 d2 = ((const int2*)(ei + NE))[e];
        atomicAdd(&g_deg[d2.x], 1);
        atomicAdd(&g_deg[d2.y], 1);
    }
}

// fused phase1+2: per-block reduce of deg+1; last block scans block sums.
__global__ void __launch_bounds__(256) scan_p1p2() {
    __shared__ int wsum[8];
    __shared__ int amLast;
    int tid = threadIdx.x, lane = tid & 31, w = tid >> 5;
    int i = blockIdx.x * 256 + tid;
    int v = (i < NN) ? g_deg[i] + 1 : 0;
    int x = v;
    #pragma unroll
    for (int d = 16; d > 0; d >>= 1) x += __shfl_down_sync(0xffffffffu, x, d);
    if (lane == 0) wsum[w] = x;
    __syncthreads();
    if (tid < 8) {
        int y = wsum[tid];
        #pragma unroll
        for (int d = 4; d > 0; d >>= 1) y += __shfl_down_sync(0xffu, y, d);
        if (tid == 0) g_bsum[blockIdx.x] = y;
    }
    if (tid == 0) {
        __threadfence();
        amLast = (atomicAdd(&g_tick, 1) == NBLK - 1) ? 1 : 0;
    }
    __syncthreads();
    if (amLast) {
        int bv = (tid < NBLK) ? g_bsum[tid] : 0;
        int bx = bv;
        #pragma unroll
        for (int d = 1; d < 32; d <<= 1) {
            int t = __shfl_up_sync(0xffffffffu, bx, d);
            if (lane >= d) bx += t;
        }
        if (lane == 31) wsum[w] = bx;
        __syncthreads();
        if (w == 0 && lane < 8) {
            int y = wsum[lane];
            #pragma unroll
            for (int d = 1; d < 8; d <<= 1) {
                int t = __shfl_up_sync(0xffu, y, d);
                if (lane >= d) y += t;
            }
            wsum[lane] = y;
        }
        __syncthreads();
        int excl = bx - bv + (w > 0 ? wsum[w - 1] : 0);
        if (tid < NBLK) g_boff[tid] = excl;
        if (tid == NBLK - 1) g_off[NN] = excl + bv;   // == ET
        if (tid == 0) g_tick = 0;
    }
}

__global__ void __launch_bounds__(256) scan_p3() {
    __shared__ int wsum[8];
    int tid = threadIdx.x, lane = tid & 31, w = tid >> 5;
    int i = blockIdx.x * 256 + tid;
    int v = 0;
    if (i < NN) {
        v = g_deg[i] + 1;
        g_dis[i] = rsqrtf((float)v);
    }
    int x = v;
    #pragma unroll
    for (int d = 1; d < 32; d <<= 1) {
        int t = __shfl_up_sync(0xffffffffu, x, d);
        if (lane >= d) x += t;
    }
    if (lane == 31) wsum[w] = x;
    __syncthreads();
    if (w == 0 && lane < 8) {
        int y = wsum[lane];
        #pragma unroll
        for (int d = 1; d < 8; d <<= 1) {
            int t = __shfl_up_sync(0xffu, y, d);
            if (lane >= d) y += t;
        }
        wsum[lane] = y;
    }
    __syncthreads();
    int excl = x - v + (w > 0 ? wsum[w - 1] : 0) + g_boff[blockIdx.x];
    if (i < NN) g_off[i] = excl;
}

__global__ void scatter_kernel(const int* __restrict__ ei) {
    int e = blockIdx.x * blockDim.x + threadIdx.x;
    if (e >= ET) return;
    int s, d;
    if (e < NE) { s = ei[e]; d = ei[NE + e]; }
    else        { s = d = e - NE; }
    int pos = g_off[d] + atomicAdd(&g_cnt[d], 1);
    g_src[pos] = s;
}

// ---------------------------------------------------------------------------
// Tensor-core GEMM 1: g_h1[M,128] = fp16( A[M,128] @ B[128,128] )
__global__ void __launch_bounds__(256) wgemm1(
    const float* __restrict__ A, const float* __restrict__ B, int M)
{
    constexpr int LDA = 40, LDB = 136;
    __shared__ __half As[128 * LDA];
    __shared__ __half Bs[32 * LDB];
    __shared__ float  cst[8][256];

    const int tid = threadIdx.x;
    const int wid = tid >> 5;
    const int lane = tid & 31;
    const int block_row = blockIdx.x * 128;
    const int warpM = wid & 3;
    const int warpN = wid >> 2;

    wmma::fragment<wmma::accumulator, 16, 16, 16, float> cf[2][4];
    #pragma unroll
    for (int i = 0; i < 2; i++)
        #pragma unroll
        for (int j = 0; j < 4; j++) wmma::fill_fragment(cf[i][j], 0.f);

    const int a_row = tid >> 1;
    const int a_cg  = (tid & 1) * 16;
    const int b_row = tid >> 3;
    const int b_cg  = (tid & 7) * 16;

    for (int t = 0; t < 4; t++) {
        int k0 = t * 32;
        {
            int grow = block_row + a_row;
            float4 v0 = make_float4(0.f,0.f,0.f,0.f), v1 = v0, v2 = v0, v3 = v0;
            if (grow < M) {
                const float4* p = (const float4*)&A[(size_t)grow * 128 + k0 + a_cg];
                v0 = p[0]; v1 = p[1]; v2 = p[2]; v3 = p[3];
            }
            uint2* dst = (uint2*)&As[a_row * LDA + a_cg];
            dst[0] = f4_to_h4(v0); dst[1] = f4_to_h4(v1);
            dst[2] = f4_to_h4(v2); dst[3] = f4_to_h4(v3);
        }
        {
            const float4* p = (const float4*)&B[(size_t)(k0 + b_row) * 128 + b_cg];
            float4 v0 = p[0], v1 = p[1], v2 = p[2], v3 = p[3];
            uint2* dst = (uint2*)&Bs[b_row * LDB + b_cg];
            dst[0] = f4_to_h4(v0); dst[1] = f4_to_h4(v1);
            dst[2] = f4_to_h4(v2); dst[3] = f4_to_h4(v3);
        }
        __syncthreads();

        #pragma unroll
        for (int ks = 0; ks < 2; ks++) {
            wmma::fragment<wmma::matrix_a, 16, 16, 16, __half, wmma::row_major> af[2];
            wmma::fragment<wmma::matrix_b, 16, 16, 16, __half, wmma::row_major> bf[4];
            #pragma unroll
            for (int i = 0; i < 2; i++)
                wmma::load_matrix_sync(af[i], &As[(warpM * 32 + i * 16) * LDA + ks * 16], LDA);
            #pragma unroll
            for (int j = 0; j < 4; j++)
                wmma::load_matrix_sync(bf[j], &Bs[(ks * 16) * LDB + warpN * 64 + j * 16], LDB);
            #pragma unroll
            for (int i = 0; i < 2; i++)
                #pragma unroll
                for (int j = 0; j < 4; j++)
                    wmma::mma_sync(cf[i][j], af[i], bf[j], cf[i][j]);
        }
        __syncthreads();
    }

    #pragma unroll
    for (int i = 0; i < 2; i++) {
        #pragma unroll
        for (int j = 0; j < 4; j++) {
            wmma::store_matrix_sync(cst[wid], cf[i][j], 16, wmma::mem_row_major);
            __syncwarp();
            int r  = lane >> 1;
            int co = (lane & 1) * 8;
            int grow = block_row + warpM * 32 + i * 16 + r;
            if (grow < M) {
                const float* s = &cst[wid][r * 16 + co];
                __half2 h[4];
                h[0] = __floats2half2_rn(s[0], s[1]);
                h[1] = __floats2half2_rn(s[2], s[3]);
                h[2] = __floats2half2_rn(s[4], s[5]);
                h[3] = __floats2half2_rn(s[6], s[7]);
                *(uint4*)&g_h1[(size_t)grow * 128 + warpN * 64 + j * 16 + co] = *(uint4*)h;
            }
            __syncwarp();
        }
    }
}

// Tensor-core GEMM 2: g_h2[M,64] = fp16( g_a1[M,128] @ B[128,64] ), A fp16.
__global__ void __launch_bounds__(256) wgemm2(
    const float* __restrict__ B, int M)
{
    constexpr int LDA = 40, LDB = 72;
    __shared__ __half As[128 * LDA];
    __shared__ __half Bs[32 * LDB];
    __shared__ float  cst[8][256];

    const int tid = threadIdx.x;
    const int wid = tid >> 5;
    const int lane = tid & 31;
    const int block_row = blockIdx.x * 128;
    const int warpM = wid & 3;
    const int warpN = wid >> 2;

    wmma::fragment<wmma::accumulator, 16, 16, 16, float> cf[2][2];
    #pragma unroll
    for (int i = 0; i < 2; i++)
        #pragma unroll
        for (int j = 0; j < 2; j++) wmma::fill_fragment(cf[i][j], 0.f);

    const int a_row = tid >> 1;
    const int a_cg  = (tid & 1) * 16;
    const int b_row = tid >> 2;
    const int b_cg  = (tid & 3) * 16;

    for (int t = 0; t < 4; t++) {
        int k0 = t * 32;
        {
            int grow = block_row + a_row;
            uint4 v0 = make_uint4(0u,0u,0u,0u), v1 = v0;
            if (grow < M) {
                const uint4* p = (const uint4*)&g_a1[(size_t)grow * 128 + k0 + a_cg];
                v0 = p[0]; v1 = p[1];
            }
            *(uint4*)&As[a_row * LDA + a_cg]     = v0;
            *(uint4*)&As[a_row * LDA + a_cg + 8] = v1;
        }
        if (b_row < 32) {
            const float4* p = (const float4*)&B[(size_t)(k0 + b_row) * 64 + b_cg];
            float4 v0 = p[0], v1 = p[1], v2 = p[2], v3 = p[3];
            uint2* dst = (uint2*)&Bs[b_row * LDB + b_cg];
            dst[0] = f4_to_h4(v0); dst[1] = f4_to_h4(v1);
            dst[2] = f4_to_h4(v2); dst[3] = f4_to_h4(v3);
        }
        __syncthreads();

        #pragma unroll
        for (int ks = 0; ks < 2; ks++) {
            wmma::fragment<wmma::matrix_a, 16, 16, 16, __half, wmma::row_major> af[2];
            wmma::fragment<wmma::matrix_b, 16, 16, 16, __half, wmma::row_major> bf[2];
            #pragma unroll
            for (int i = 0; i < 2; i++)
                wmma::load_matrix_sync(af[i], &As[(warpM * 32 + i * 16) * LDA + ks * 16], LDA);
            #pragma unroll
            for (int j = 0; j < 2; j++)
                wmma::load_matrix_sync(bf[j], &Bs[(ks * 16) * LDB + warpN * 32 + j * 16], LDB);
            #pragma unroll
            for (int i = 0; i < 2; i++)
                #pragma unroll
                for (int j = 0; j < 2; j++)
                    wmma::mma_sync(cf[i][j], af[i], bf[j], cf[i][j]);
        }
        __syncthreads();
    }

    #pragma unroll
    for (int i = 0; i < 2; i++) {
        #pragma unroll
        for (int j = 0; j < 2; j++) {
            wmma::store_matrix_sync(cst[wid], cf[i][j], 16, wmma::mem_row_major);
            __syncwarp();
            int r  = lane >> 1;
            int co = (lane & 1) * 8;
            int grow = block_row + warpM * 32 + i * 16 + r;
            if (grow < M) {
                const float* s = &cst[wid][r * 16 + co];
                __half2 h[4];
                h[0] = __floats2half2_rn(s[0], s[1]);
                h[1] = __floats2half2_rn(s[2], s[3]);
                h[2] = __floats2half2_rn(s[4], s[5]);
                h[3] = __floats2half2_rn(s[6], s[7]);
                *(uint4*)&g_h2[(size_t)grow * 64 + warpN * 32 + j * 16 + co] = *(uint4*)h;
            }
            __syncwarp();
        }
    }
}

// ---------------------------------------------------------------------------
// Segment aggregation: warp per node; fp16 gathers, fp32 accumulate,
// fp16 store of a1.
__global__ void __launch_bounds__(256) agg128_relu(
    const float* __restrict__ bias)
{
    int gw = (blockIdx.x * blockDim.x + threadIdx.x) >> 5;
    int lane = threadIdx.x & 31;
    if (gw >= NN) return;
    int beg = g_off[gw], end = g_off[gw + 1];
    int c4 = lane * 4;

    float4 acc = make_float4(0.f, 0.f, 0.f, 0.f);
    int idx = beg;
    for (; idx + 4 <= end; idx += 4) {
        int s0 = g_src[idx + 0];
        int s1 = g_src[idx + 1];
        int s2 = g_src[idx + 2];
        int s3 = g_src[idx + 3];
        float n0 = g_dis[s0], n1 = g_dis[s1], n2 = g_dis[s2], n3 = g_dis[s3];
        uint2 u0 = *(const uint2*)(g_h1 + (size_t)s0 * 128 + c4);
        uint2 u1 = *(const uint2*)(g_h1 + (size_t)s1 * 128 + c4);
        uint2 u2 = *(const uint2*)(g_h1 + (size_t)s2 * 128 + c4);
        uint2 u3 = *(const uint2*)(g_h1 + (size_t)s3 * 128 + c4);
        float4 v0 = h4_to_f4(u0);
        float4 v1 = h4_to_f4(u1);
        float4 v2 = h4_to_f4(u2);
        float4 v3 = h4_to_f4(u3);
        acc.x = fmaf(n0, v0.x, acc.x); acc.y = fmaf(n0, v0.y, acc.y);
        acc.z = fmaf(n0, v0.z, acc.z); acc.w = fmaf(n0, v0.w, acc.w);
        acc.x = fmaf(n1, v1.x, acc.x); acc.y = fmaf(n1, v1.y, acc.y);
        acc.z = fmaf(n1, v1.z, acc.z); acc.w = fmaf(n1, v1.w, acc.w);
        acc.x = fmaf(n2, v2.x, acc.x); acc.y = fmaf(n2, v2.y, acc.y);
        acc.z = fmaf(n2, v2.z, acc.z); acc.w = fmaf(n2, v2.w, acc.w);
        acc.x = fmaf(n3, v3.x, acc.x); acc.y = fmaf(n3, v3.y, acc.y);
        acc.z = fmaf(n3, v3.z, acc.z); acc.w = fmaf(n3, v3.w, acc.w);
    }
    for (; idx < end; idx++) {
        int s = g_src[idx];
        float n = g_dis[s];
        float4 v = h4_to_f4(*(const uint2*)(g_h1 + (size_t)s * 128 + c4));
        acc.x = fmaf(n, v.x, acc.x); acc.y = fmaf(n, v.y, acc.y);
        acc.z = fmaf(n, v.z, acc.z); acc.w = fmaf(n, v.w, acc.w);
    }
    float dd = g_dis[gw];
    float4 bb = *(const float4*)(bias + c4);
    acc.x = fmaxf(fmaf(dd, acc.x, bb.x), 0.f);
    acc.y = fmaxf(fmaf(dd, acc.y, bb.y), 0.f);
    acc.z = fmaxf(fmaf(dd, acc.z, bb.z), 0.f);
    acc.w = fmaxf(fmaf(dd, acc.w, bb.w), 0.f);
    *(uint2*)&g_a1[(size_t)gw * 128 + c4] = f4_to_h4(acc);
}

// last kernel: also zeroes g_deg/g_cnt for the next launch
__global__ void __launch_bounds__(256) agg64_out(
    const float* __restrict__ bias, float* __restrict__ OUT)
{
    int gw = (blockIdx.x * blockDim.x + threadIdx.x) >> 5;
    int lane = threadIdx.x & 31;
    if (gw >= NN) return;
    int beg = g_off[gw], end = g_off[gw + 1];
    int c2 = lane * 2;

    float2 acc = make_float2(0.f, 0.f);
    int idx = beg;
    for (; idx + 4 <= end; idx += 4) {
        int s0 = g_src[idx + 0];
        int s1 = g_src[idx + 1];
        int s2 = g_src[idx + 2];
        int s3 = g_src[idx + 3];
        float n0 = g_dis[s0], n1 = g_dis[s1], n2 = g_dis[s2], n3 = g_dis[s3];
        float2 v0 = h2_to_f2(*(const unsigned*)(g_h2 + (size_t)s0 * 64 + c2));
        float2 v1 = h2_to_f2(*(const unsigned*)(g_h2 + (size_t)s1 * 64 + c2));
        float2 v2 = h2_to_f2(*(const unsigned*)(g_h2 + (size_t)s2 * 64 + c2));
        float2 v3 = h2_to_f2(*(const unsigned*)(g_h2 + (size_t)s3 * 64 + c2));
        acc.x = fmaf(n0, v0.x, acc.x); acc.y = fmaf(n0, v0.y, acc.y);
        acc.x = fmaf(n1, v1.x, acc.x); acc.y = fmaf(n1, v1.y, acc.y);
        acc.x = fmaf(n2, v2.x, acc.x); acc.y = fmaf(n2, v2.y, acc.y);
        acc.x = fmaf(n3, v3.x, acc.x); acc.y = fmaf(n3, v3.y, acc.y);
    }
    for (; idx < end; idx++) {
        int s = g_src[idx];
        float n = g_dis[s];
        float2 v = h2_to_f2(*(const unsigned*)(g_h2 + (size_t)s * 64 + c2));
        acc.x = fmaf(n, v.x, acc.x); acc.y = fmaf(n, v.y, acc.y);
    }
    float dd = g_dis[gw];
    float2 bb = *(const float2*)(bias + c2);
    acc.x = fmaf(dd, acc.x, bb.x);
    acc.y = fmaf(dd, acc.y, bb.y);
    *(float2*)(OUT + (size_t)gw * 64 + c2) = acc;

    if (lane == 0) { g_deg[gw] = 0; g_cnt[gw] = 0; }
}

// ---------------------------------------------------------------------------
extern "C" void kernel_launch(void* const* d_in, const int* in_sizes, int n_in,
                              void* d_out, int out_size) {
    const float* x  = (const float*)d_in[0];
    const int*   ei = (const int*)d_in[1];
    const float* W1 = (const float*)d_in[2];
    const float* b1 = (const float*)d_in[3];
    const float* W2 = (const float*)d_in[4];
    const float* b2 = (const float*)d_in[5];
    float*       out = (float*)d_out;

    static cudaStream_t s2 = nullptr;
    static cudaEvent_t evFork = nullptr, evJoin = nullptr;
    if (s2 == nullptr) {
        cudaStreamCreateWithFlags(&s2, cudaStreamNonBlocking);
        cudaEventCreateWithFlags(&evFork, cudaEventDisableTiming);
        cudaEventCreateWithFlags(&evJoin, cudaEventDisableTiming);
    }

    const int TB = 256;

    // fork: wgemm1 (x@W1, independent of graph prep) on s2
    cudaEventRecord(evFork, 0);
    cudaStreamWaitEvent(s2, evFork, 0);
    wgemm1<<<(NN + 127) / 128, 256, 0, s2>>>(x, W1, NN);
    cudaEventRecord(evJoin, s2);

    // graph prep on main stream
    degree_kernel<<<(NE / 2 + TB - 1) / TB, TB>>>(ei);
    scan_p1p2<<<NBLK, 256>>>();
    scan_p3<<<NBLK, 256>>>();
    scatter_kernel<<<(ET + TB - 1) / TB, TB>>>(ei);

    // join, then rest of the pipeline
    cudaStreamWaitEvent(0, evJoin, 0);
    agg128_relu<<<(NN * 32 + TB - 1) / TB, TB>>>(b1);
    wgemm2<<<(NN + 127) / 128, 256>>>(W2, NN);
    agg64_out<<<(NN * 32 + TB - 1) / TB, TB>>>(b2, out);
}

// round 17
// speedup vs baseline: 1.1344x; 1.0019x over previous
#include <cuda_runtime.h>
#include <cuda_bf16.h>
#include <cuda_fp16.h>
#include <mma.h>

using namespace nvcuda;

// 2-layer GCN. Ahat = D^-1/2 (A+I) D^-1/2, factored:
//   agg(h)[d] = dis[d] * sum_{s in N(d)} dis[s] * h[s]
// int32 edges; counting-sort by dst; warp-per-node segment aggregation with
// fp16 gathers; WMMA fp16 GEMMs (fp32 accumulate); fp16 intermediates.
// wgemm2: 128-thr/BM=64 for occupancy. degree/scatter vectorized.

#define NN 50000
#define NE 800000
#define ET (NN + NE)
#define NBLK ((NN + 255) / 256)

// ---- device scratch (static, no allocation) ----
__device__ __half g_h1[NN * 128];    // fp16 x@W1
__device__ __half g_a1[NN * 128];    // fp16 relu(agg)
__device__ __half g_h2[NN * 64];     // fp16 a1@W2
__device__ int    g_deg[NN];         // zeroed by tail of previous launch
__device__ float  g_dis[NN];
__device__ int    g_off[NN + 1];
__device__ int    g_cnt[NN];         // zeroed by tail of previous launch
__device__ int    g_src[ET];
__device__ int    g_bsum[NBLK];
__device__ int    g_boff[NBLK];
__device__ int    g_tick;            // reset by last scan block

__device__ __forceinline__ float4 h4_to_f4(uint2 u) {
    __half2 a = *reinterpret_cast<__half2*>(&u.x);
    __half2 b = *reinterpret_cast<__half2*>(&u.y);
    float2 fa = __half22float2(a), fb = __half22float2(b);
    return make_float4(fa.x, fa.y, fb.x, fb.y);
}
__device__ __forceinline__ float2 h2_to_f2(unsigned u) {
    __half2 a = *reinterpret_cast<__half2*>(&u);
    return __half22float2(a);
}
__device__ __forceinline__ uint2 f4_to_h4(float4 v) {
    __half2 h0 = __floats2half2_rn(v.x, v.y);
    __half2 h1 = __floats2half2_rn(v.z, v.w);
    uint2 r;
    r.x = *reinterpret_cast<unsigned*>(&h0);
    r.y = *reinterpret_cast<unsigned*>(&h1);
    return r;
}

// ---------------------------------------------------------------------------
__global__ void degree_kernel(const int* __restrict__ ei) {
    int e = blockIdx.x * blockDim.x + threadIdx.x;   // 4 edges/thread
    if (e < NE / 4) {
        int4 d4 = ((const int4*)(ei + NE))[e];
        atomicAdd(&g_deg[d4.x], 1);
        atomicAdd(&g_deg[d4.y], 1);
        atomicAdd(&g_deg[d4.z], 1);
        atomicAdd(&g_deg[d4.w], 1);
    }
}

// fused phase1+2: per-block reduce of deg+1; last block scans block sums.
__global__ void __launch_bounds__(256) scan_p1p2() {
    __shared__ int wsum[8];
    __shared__ int amLast;
    int tid = threadIdx.x, lane = tid & 31, w = tid >> 5;
    int i = blockIdx.x * 256 + tid;
    int v = (i < NN) ? g_deg[i] + 1 : 0;
    int x = v;
    #pragma unroll
    for (int d = 16; d > 0; d >>= 1) x += __shfl_down_sync(0xffffffffu, x, d);
    if (lane == 0) wsum[w] = x;
    __syncthreads();
    if (tid < 8) {
        int y = wsum[tid];
        #pragma unroll
        for (int d = 4; d > 0; d >>= 1) y += __shfl_down_sync(0xffu, y, d);
        if (tid == 0) g_bsum[blockIdx.x] = y;
    }
    if (tid == 0) {
        __threadfence();
        amLast = (atomicAdd(&g_tick, 1) == NBLK - 1) ? 1 : 0;
    }
    __syncthreads();
    if (amLast) {
        int bv = (tid < NBLK) ? g_bsum[tid] : 0;
        int bx = bv;
        #pragma unroll
        for (int d = 1; d < 32; d <<= 1) {
            int t = __shfl_up_sync(0xffffffffu, bx, d);
            if (lane >= d) bx += t;
        }
        if (lane == 31) wsum[w] = bx;
        __syncthreads();
        if (w == 0 && lane < 8) {
            int y = wsum[lane];
            #pragma unroll
            for (int d = 1; d < 8; d <<= 1) {
                int t = __shfl_up_sync(0xffu, y, d);
                if (lane >= d) y += t;
            }
            wsum[lane] = y;
        }
        __syncthreads();
        int excl = bx - bv + (w > 0 ? wsum[w - 1] : 0);
        if (tid < NBLK) g_boff[tid] = excl;
        if (tid == NBLK - 1) g_off[NN] = excl + bv;   // == ET
        if (tid == 0) g_tick = 0;
    }
}

__global__ void __launch_bounds__(256) scan_p3() {
    __shared__ int wsum[8];
    int tid = threadIdx.x, lane = tid & 31, w = tid >> 5;
    int i = blockIdx.x * 256 + tid;
    int v = 0;
    if (i < NN) {
        v = g_deg[i] + 1;
        g_dis[i] = rsqrtf((float)v);
    }
    int x = v;
    #pragma unroll
    for (int d = 1; d < 32; d <<= 1) {
        int t = __shfl_up_sync(0xffffffffu, x, d);
        if (lane >= d) x += t;
    }
    if (lane == 31) wsum[w] = x;
    __syncthreads();
    if (w == 0 && lane < 8) {
        int y = wsum[lane];
        #pragma unroll
        for (int d = 1; d < 8; d <<= 1) {
            int t = __shfl_up_sync(0xffu, y, d);
            if (lane >= d) y += t;
        }
        wsum[lane] = y;
    }
    __syncthreads();
    int excl = x - v + (w > 0 ? wsum[w - 1] : 0) + g_boff[blockIdx.x];
    if (i < NN) g_off[i] = excl;
}

// scatter: threads [0, NE/2) handle 2 real edges via int2; the next NN
// threads handle one self loop each.
__global__ void scatter_kernel(const int* __restrict__ ei) {
    int t = blockIdx.x * blockDim.x + threadIdx.x;
    if (t < NE / 2) {
        int2 s2 = ((const int2*)ei)[t];
        int2 d2 = ((const int2*)(ei + NE))[t];
        int p0 = g_off[d2.x] + atomicAdd(&g_cnt[d2.x], 1);
        int p1 = g_off[d2.y] + atomicAdd(&g_cnt[d2.y], 1);
        g_src[p0] = s2.x;
        g_src[p1] = s2.y;
    } else {
        int n = t - NE / 2;
        if (n < NN) {
            int pos = g_off[n] + atomicAdd(&g_cnt[n], 1);
            g_src[pos] = n;
        }
    }
}

// ---------------------------------------------------------------------------
// Tensor-core GEMM 1: g_h1[M,128] = fp16( A[M,128] @ B[128,128] )
__global__ void __launch_bounds__(256) wgemm1(
    const float* __restrict__ A, const float* __restrict__ B, int M)
{
    constexpr int LDA = 40, LDB = 136;
    __shared__ __half As[128 * LDA];
    __shared__ __half Bs[32 * LDB];
    __shared__ float  cst[8][256];

    const int tid = threadIdx.x;
    const int wid = tid >> 5;
    const int lane = tid & 31;
    const int block_row = blockIdx.x * 128;
    const int warpM = wid & 3;
    const int warpN = wid >> 2;

    wmma::fragment<wmma::accumulator, 16, 16, 16, float> cf[2][4];
    #pragma unroll
    for (int i = 0; i < 2; i++)
        #pragma unroll
        for (int j = 0; j < 4; j++) wmma::fill_fragment(cf[i][j], 0.f);

    const int a_row = tid >> 1;
    const int a_cg  = (tid & 1) * 16;
    const int b_row = tid >> 3;
    const int b_cg  = (tid & 7) * 16;

    for (int t = 0; t < 4; t++) {
        int k0 = t * 32;
        {
            int grow = block_row + a_row;
            float4 v0 = make_float4(0.f,0.f,0.f,0.f), v1 = v0, v2 = v0, v3 = v0;
            if (grow < M) {
                const float4* p = (const float4*)&A[(size_t)grow * 128 + k0 + a_cg];
                v0 = p[0]; v1 = p[1]; v2 = p[2]; v3 = p[3];
            }
            uint2* dst = (uint2*)&As[a_row * LDA + a_cg];
            dst[0] = f4_to_h4(v0); dst[1] = f4_to_h4(v1);
            dst[2] = f4_to_h4(v2); dst[3] = f4_to_h4(v3);
        }
        {
            const float4* p = (const float4*)&B[(size_t)(k0 + b_row) * 128 + b_cg];
            float4 v0 = p[0], v1 = p[1], v2 = p[2], v3 = p[3];
            uint2* dst = (uint2*)&Bs[b_row * LDB + b_cg];
            dst[0] = f4_to_h4(v0); dst[1] = f4_to_h4(v1);
            dst[2] = f4_to_h4(v2); dst[3] = f4_to_h4(v3);
        }
        __syncthreads();

        #pragma unroll
        for (int ks = 0; ks < 2; ks++) {
            wmma::fragment<wmma::matrix_a, 16, 16, 16, __half, wmma::row_major> af[2];
            wmma::fragment<wmma::matrix_b, 16, 16, 16, __half, wmma::row_major> bf[4];
            #pragma unroll
            for (int i = 0; i < 2; i++)
                wmma::load_matrix_sync(af[i], &As[(warpM * 32 + i * 16) * LDA + ks * 16], LDA);
            #pragma unroll
            for (int j = 0; j < 4; j++)
                wmma::load_matrix_sync(bf[j], &Bs[(ks * 16) * LDB + warpN * 64 + j * 16], LDB);
            #pragma unroll
            for (int i = 0; i < 2; i++)
                #pragma unroll
                for (int j = 0; j < 4; j++)
                    wmma::mma_sync(cf[i][j], af[i], bf[j], cf[i][j]);
        }
        __syncthreads();
    }

    #pragma unroll
    for (int i = 0; i < 2; i++) {
        #pragma unroll
        for (int j = 0; j < 4; j++) {
            wmma::store_matrix_sync(cst[wid], cf[i][j], 16, wmma::mem_row_major);
            __syncwarp();
            int r  = lane >> 1;
            int co = (lane & 1) * 8;
            int grow = block_row + warpM * 32 + i * 16 + r;
            if (grow < M) {
                const float* s = &cst[wid][r * 16 + co];
                __half2 h[4];
                h[0] = __floats2half2_rn(s[0], s[1]);
                h[1] = __floats2half2_rn(s[2], s[3]);
                h[2] = __floats2half2_rn(s[4], s[5]);
                h[3] = __floats2half2_rn(s[6], s[7]);
                *(uint4*)&g_h1[(size_t)grow * 128 + warpN * 64 + j * 16 + co] = *(uint4*)h;
            }
            __syncwarp();
        }
    }
}

// Tensor-core GEMM 2: g_h2[M,64] = fp16( g_a1[M,128] @ B[128,64] ), A fp16.
// 128 threads, BM=64, 4 warps (2 M x 2 N), warp tile 32x32 — occupancy fix.
__global__ void __launch_bounds__(128) wgemm2(
    const float* __restrict__ B, int M)
{
    constexpr int LDA = 40, LDB = 72;
    __shared__ __half As[64 * LDA];
    __shared__ __half Bs[32 * LDB];
    __shared__ float  cst[4][256];

    const int tid = threadIdx.x;
    const int wid = tid >> 5;
    const int lane = tid & 31;
    const int block_row = blockIdx.x * 64;
    const int warpM = wid & 1;
    const int warpN = wid >> 1;

    wmma::fragment<wmma::accumulator, 16, 16, 16, float> cf[2][2];
    #pragma unroll
    for (int i = 0; i < 2; i++)
        #pragma unroll
        for (int j = 0; j < 2; j++) wmma::fill_fragment(cf[i][j], 0.f);

    const int a_row = tid >> 1;          // 0..63
    const int a_cg  = (tid & 1) * 16;    // halves
    const int b_row = tid >> 2;          // 0..31
    const int b_cg  = (tid & 3) * 16;    // floats

    for (int t = 0; t < 4; t++) {
        int k0 = t * 32;
        {
            int grow = block_row + a_row;
            uint4 v0 = make_uint4(0u,0u,0u,0u), v1 = v0;
            if (grow < M) {
                const uint4* p = (const uint4*)&g_a1[(size_t)grow * 128 + k0 + a_cg];
                v0 = p[0]; v1 = p[1];
            }
            *(uint4*)&As[a_row * LDA + a_cg]     = v0;
            *(uint4*)&As[a_row * LDA + a_cg + 8] = v1;
        }
        {
            const float4* p = (const float4*)&B[(size_t)(k0 + b_row) * 64 + b_cg];
            float4 v0 = p[0], v1 = p[1], v2 = p[2], v3 = p[3];
            uint2* dst = (uint2*)&Bs[b_row * LDB + b_cg];
            dst[0] = f4_to_h4(v0); dst[1] = f4_to_h4(v1);
            dst[2] = f4_to_h4(v2); dst[3] = f4_to_h4(v3);
        }
        __syncthreads();

        #pragma unroll
        for (int ks = 0; ks < 2; ks++) {
            wmma::fragment<wmma::matrix_a, 16, 16, 16, __half, wmma::row_major> af[2];
            wmma::fragment<wmma::matrix_b, 16, 16, 16, __half, wmma::row_major> bf[2];
            #pragma unroll
            for (int i = 0; i < 2; i++)
                wmma::load_matrix_sync(af[i], &As[(warpM * 32 + i * 16) * LDA + ks * 16], LDA);
            #pragma unroll
            for (int j = 0; j < 2; j++)
                wmma::load_matrix_sync(bf[j], &Bs[(ks * 16) * LDB + warpN * 32 + j * 16], LDB);
            #pragma unroll
            for (int i = 0; i < 2; i++)
                #pragma unroll
                for (int j = 0; j < 2; j++)
                    wmma::mma_sync(cf[i][j], af[i], bf[j], cf[i][j]);
        }
        __syncthreads();
    }

    #pragma unroll
    for (int i = 0; i < 2; i++) {
        #pragma unroll
        for (int j = 0; j < 2; j++) {
            wmma::store_matrix_sync(cst[wid], cf[i][j], 16, wmma::mem_row_major);
            __syncwarp();
            int r  = lane >> 1;
            int co = (lane & 1) * 8;
            int grow = block_row + warpM * 32 + i * 16 + r;
            if (grow < M) {
                const float* s = &cst[wid][r * 16 + co];
                __half2 h[4];
                h[0] = __floats2half2_rn(s[0], s[1]);
                h[1] = __floats2half2_rn(s[2], s[3]);
                h[2] = __floats2half2_rn(s[4], s[5]);
                h[3] = __floats2half2_rn(s[6], s[7]);
                *(uint4*)&g_h2[(size_t)grow * 64 + warpN * 32 + j * 16 + co] = *(uint4*)h;
            }
            __syncwarp();
        }
    }
}

// ---------------------------------------------------------------------------
// Segment aggregation: warp per node; fp16 gathers, fp32 accumulate,
// fp16 store of a1.
__global__ void __launch_bounds__(256) agg128_relu(
    const float* __restrict__ bias)
{
    int gw = (blockIdx.x * blockDim.x + threadIdx.x) >> 5;
    int lane = threadIdx.x & 31;
    if (gw >= NN) return;
    int beg = g_off[gw], end = g_off[gw + 1];
    int c4 = lane * 4;

    float4 acc = make_float4(0.f, 0.f, 0.f, 0.f);
    int idx = beg;
    for (; idx + 4 <= end; idx += 4) {
        int s0 = g_src[idx + 0];
        int s1 = g_src[idx + 1];
        int s2 = g_src[idx + 2];
        int s3 = g_src[idx + 3];
        float n0 = g_dis[s0], n1 = g_dis[s1], n2 = g_dis[s2], n3 = g_dis[s3];
        uint2 u0 = *(const uint2*)(g_h1 + (size_t)s0 * 128 + c4);
        uint2 u1 = *(const uint2*)(g_h1 + (size_t)s1 * 128 + c4);
        uint2 u2 = *(const uint2*)(g_h1 + (size_t)s2 * 128 + c4);
        uint2 u3 = *(const uint2*)(g_h1 + (size_t)s3 * 128 + c4);
        float4 v0 = h4_to_f4(u0);
        float4 v1 = h4_to_f4(u1);
        float4 v2 = h4_to_f4(u2);
        float4 v3 = h4_to_f4(u3);
        acc.x = fmaf(n0, v0.x, acc.x); acc.y = fmaf(n0, v0.y, acc.y);
        acc.z = fmaf(n0, v0.z, acc.z); acc.w = fmaf(n0, v0.w, acc.w);
        acc.x = fmaf(n1, v1.x, acc.x); acc.y = fmaf(n1, v1.y, acc.y);
        acc.z = fmaf(n1, v1.z, acc.z); acc.w = fmaf(n1, v1.w, acc.w);
        acc.x = fmaf(n2, v2.x, acc.x); acc.y = fmaf(n2, v2.y, acc.y);
        acc.z = fmaf(n2, v2.z, acc.z); acc.w = fmaf(n2, v2.w, acc.w);
        acc.x = fmaf(n3, v3.x, acc.x); acc.y = fmaf(n3, v3.y, acc.y);
        acc.z = fmaf(n3, v3.z, acc.z); acc.w = fmaf(n3, v3.w, acc.w);
    }
    for (; idx < end; idx++) {
        int s = g_src[idx];
        float n = g_dis[s];
        float4 v = h4_to_f4(*(const uint2*)(g_h1 + (size_t)s * 128 + c4));
        acc.x = fmaf(n, v.x, acc.x); acc.y = fmaf(n, v.y, acc.y);
        acc.z = fmaf(n, v.z, acc.z); acc.w = fmaf(n, v.w, acc.w);
    }
    float dd = g_dis[gw];
    float4 bb = *(const float4*)(bias + c4);
    acc.x = fmaxf(fmaf(dd, acc.x, bb.x), 0.f);
    acc.y = fmaxf(fmaf(dd, acc.y, bb.y), 0.f);
    acc.z = fmaxf(fmaf(dd, acc.z, bb.z), 0.f);
    acc.w = fmaxf(fmaf(dd, acc.w, bb.w), 0.f);
    *(uint2*)&g_a1[(size_t)gw * 128 + c4] = f4_to_h4(acc);
}

// last kernel: also zeroes g_deg/g_cnt for the next launch
__global__ void __launch_bounds__(256) agg64_out(
    const float* __restrict__ bias, float* __restrict__ OUT)
{
    int gw = (blockIdx.x * blockDim.x + threadIdx.x) >> 5;
    int lane = threadIdx.x & 31;
    if (gw >= NN) return;
    int beg = g_off[gw], end = g_off[gw + 1];
    int c2 = lane * 2;

    float2 acc = make_float2(0.f, 0.f);
    int idx = beg;
    for (; idx + 4 <= end; idx += 4) {
        int s0 = g_src[idx + 0];
        int s1 = g_src[idx + 1];
        int s2 = g_src[idx + 2];
        int s3 = g_src[idx + 3];
        float n0 = g_dis[s0], n1 = g_dis[s1], n2 = g_dis[s2], n3 = g_dis[s3];
        float2 v0 = h2_to_f2(*(const unsigned*)(g_h2 + (size_t)s0 * 64 + c2));
        float2 v1 = h2_to_f2(*(const unsigned*)(g_h2 + (size_t)s1 * 64 + c2));
        float2 v2 = h2_to_f2(*(const unsigned*)(g_h2 + (size_t)s2 * 64 + c2));
        float2 v3 = h2_to_f2(*(const unsigned*)(g_h2 + (size_t)s3 * 64 + c2));
        acc.x = fmaf(n0, v0.x, acc.x); acc.y = fmaf(n0, v0.y, acc.y);
        acc.x = fmaf(n1, v1.x, acc.x); acc.y = fmaf(n1, v1.y, acc.y);
        acc.x = fmaf(n2, v2.x, acc.x); acc.y = fmaf(n2, v2.y, acc.y);
        acc.x = fmaf(n3, v3.x, acc.x); acc.y = fmaf(n3, v3.y, acc.y);
    }
    for (; idx < end; idx++) {
        int s = g_src[idx];
        float n = g_dis[s];
        float2 v = h2_to_f2(*(const unsigned*)(g_h2 + (size_t)s * 64 + c2));
        acc.x = fmaf(n, v.x, acc.x); acc.y = fmaf(n, v.y, acc.y);
    }
    float dd = g_dis[gw];
    float2 bb = *(const float2*)(bias + c2);
    acc.x = fmaf(dd, acc.x, bb.x);
    acc.y = fmaf(dd, acc.y, bb.y);
    *(float2*)(OUT + (size_t)gw * 64 + c2) = acc;

    if (lane == 0) { g_deg[gw] = 0; g_cnt[gw] = 0; }
}

// ---------------------------------------------------------------------------
extern "C" void kernel_launch(void* const* d_in, const int* in_sizes, int n_in,
                              void* d_out, int out_size) {
    const float* x  = (const float*)d_in[0];
    const int*   ei = (const int*)d_in[1];
    const float* W1 = (const float*)d_in[2];
    const float* b1 = (const float*)d_in[3];
    const float* W2 = (const float*)d_in[4];
    const float* b2 = (const float*)d_in[5];
    float*       out = (float*)d_out;

    static cudaStream_t s2 = nullptr;
    static cudaEvent_t evFork = nullptr, evJoin = nullptr;
    if (s2 == nullptr) {
        cudaStreamCreateWithFlags(&s2, cudaStreamNonBlocking);
        cudaEventCreateWithFlags(&evFork, cudaEventDisableTiming);
        cudaEventCreateWithFlags(&evJoin, cudaEventDisableTiming);
    }

    const int TB = 256;

    // fork: wgemm1 (x@W1, independent of graph prep) on s2
    cudaEventRecord(evFork, 0);
    cudaStreamWaitEvent(s2, evFork, 0);
    wgemm1<<<(NN + 127) / 128, 256, 0, s2>>>(x, W1, NN);
    cudaEventRecord(evJoin, s2);

    // graph prep on main stream
    degree_kernel<<<(NE / 4 + TB - 1) / TB, TB>>>(ei);
    scan_p1p2<<<NBLK, 256>>>();
    scan_p3<<<NBLK, 256>>>();
    scatter_kernel<<<(NE / 2 + NN + TB - 1) / TB, TB>>>(ei);

    // join, then rest of the pipeline
    cudaStreamWaitEvent(0, evJoin, 0);
    agg128_relu<<<(NN * 32 + TB - 1) / TB, TB>>>(b1);
    wgemm2<<<(NN + 63) / 64, 128>>>(W2, NN);
    agg64_out<<<(NN * 32 + TB - 1) / TB, TB>>>(b2, out);
}